// round 17
// baseline (speedup 1.0000x reference)
#include <cuda_runtime.h>
#include <cuda_fp16.h>
#include <cstdint>

#define TT 1024
#define BB 4
#define DIM 1024
#define NH 16
#define HD 64
#define NTOK (TT * BB)     // 4096 tokens
#define ROWSTR (BB * DIM)  // 4096 floats per t-step

// ---------------- scratch (device globals; no allocations allowed) --------
__device__ float g_q[NTOK * DIM];
__device__ float g_k[NTOK * DIM];
__device__ float g_v[NTOK * DIM];
__device__ float g_ctx[NTOK * DIM];
__device__ float g_t1[NTOK * DIM];
__device__ float g_h[NTOK * DIM];
__device__ float g_t2[NTOK * DIM];

// ===========================================================================
// helpers
// ===========================================================================
__device__ __forceinline__ void mma16816(float* c, const uint32_t* a,
                                         const uint32_t* b) {
    asm volatile(
        "mma.sync.aligned.m16n8k16.row.col.f32.f16.f16.f32 "
        "{%0,%1,%2,%3}, {%4,%5,%6,%7}, {%8,%9}, {%0,%1,%2,%3};"
        : "+f"(c[0]), "+f"(c[1]), "+f"(c[2]), "+f"(c[3])
        : "r"(a[0]), "r"(a[1]), "r"(a[2]), "r"(a[3]), "r"(b[0]), "r"(b[1]));
}

__device__ __forceinline__ uint32_t pack2(float v0, float v1) {
    __half2 p = __floats2half2_rn(v0, v1);
    return *(uint32_t*)&p;
}

// ===========================================================================
// GEMM via mma.sync pure fp16 (1 pass): C = Ah @ Bh^T + bias.
// 128x128 tile, BK=32, 8 warps (2x4), double buffer, occ 2.
// smem per stage: Ah, Bh tiles of 128x32 fp16 padded to 80B rows.
// ===========================================================================
#define TILEB (128 * 80)
#define STAGEB (2 * TILEB)
#define GEMM_SMEM (2 * STAGEB)   // 40960 B

__device__ __forceinline__ void gemm_body(const float* __restrict__ A,
                                          const float* __restrict__ W,
                                          const float* __restrict__ bias,
                                          float* __restrict__ C, char* sm) {
    const int tid = threadIdx.x;
    const int wid = tid >> 5;
    const int lane = tid & 31;
    const int laneR = lane >> 2;
    const int laneC = lane & 3;
    const int mBase = (wid >> 2) * 64;
    const int nBase = (wid & 3) * 32;
    const int m0 = blockIdx.y * 128;
    const int n0 = blockIdx.x * 128;

    const int lrow = tid >> 3;
    const int lc4 = (tid & 7) << 2;

    float acc[4][4][4];
#pragma unroll
    for (int i = 0; i < 4; i++)
#pragma unroll
        for (int j = 0; j < 4; j++)
#pragma unroll
            for (int r = 0; r < 4; r++) acc[i][j][r] = 0.f;

    float4 ra[4], rb[4];

    auto load_g = [&](int ch) {
        const int k0 = ch * 32;
#pragma unroll
        for (int it = 0; it < 4; it++) {
            int row = lrow + it * 32;
            ra[it] = *(const float4*)(A + (size_t)(m0 + row) * DIM + k0 + lc4);
            rb[it] = *(const float4*)(W + (size_t)(n0 + row) * DIM + k0 + lc4);
        }
    };

    auto cvt_store = [&](int b) {
        char* st = sm + b * STAGEB;
#pragma unroll
        for (int it = 0; it < 4; it++) {
            int row = lrow + it * 32;
            uint32_t bo = row * 80 + lc4 * 2;
            uint2 uh;
            uh.x = pack2(ra[it].x, ra[it].y);
            uh.y = pack2(ra[it].z, ra[it].w);
            *(uint2*)(st + bo) = uh;                    // Ah
            uh.x = pack2(rb[it].x, rb[it].y);
            uh.y = pack2(rb[it].z, rb[it].w);
            *(uint2*)(st + TILEB + bo) = uh;            // Bh
        }
    };

    auto mma_stage = [&](int b) {
        const char* sb = sm + b * STAGEB;
#pragma unroll
        for (int s = 0; s < 2; s++) {
            const uint32_t so = s * 32 + laneC * 4;
            uint32_t bh[4][2];
#pragma unroll
            for (int tj = 0; tj < 4; tj++) {
                uint32_t r = (nBase + tj * 8 + laneR) * 80 + so;
                bh[tj][0] = *(const uint32_t*)(sb + TILEB + r);
                bh[tj][1] = *(const uint32_t*)(sb + TILEB + r + 16);
            }
#pragma unroll
            for (int ti = 0; ti < 4; ti++) {
                uint32_t r = (mBase + ti * 16 + laneR) * 80 + so;
                uint32_t ah[4];
                ah[0] = *(const uint32_t*)(sb + r);
                ah[1] = *(const uint32_t*)(sb + r + 640);
                ah[2] = *(const uint32_t*)(sb + r + 16);
                ah[3] = *(const uint32_t*)(sb + r + 656);
#pragma unroll
                for (int tj = 0; tj < 4; tj++) {
                    mma16816(acc[ti][tj], ah, bh[tj]);
                }
            }
        }
    };

    load_g(0);
    cvt_store(0);
    __syncthreads();

    for (int ch = 0; ch < 32; ch++) {
        const int b = ch & 1;
        if (ch < 31) load_g(ch + 1);
        mma_stage(b);
        if (ch < 31) cvt_store(b ^ 1);
        __syncthreads();
    }

#pragma unroll
    for (int ti = 0; ti < 4; ti++) {
        const int row = m0 + mBase + ti * 16 + laneR;
#pragma unroll
        for (int tj = 0; tj < 4; tj++) {
            const int col = n0 + nBase + tj * 8 + laneC * 2;
            const float b0 = __ldg(bias + col);
            const float b1 = __ldg(bias + col + 1);
            float2 o0 = make_float2(acc[ti][tj][0] + b0, acc[ti][tj][1] + b1);
            float2 o1 = make_float2(acc[ti][tj][2] + b0, acc[ti][tj][3] + b1);
            *(float2*)(C + (size_t)row * DIM + col) = o0;
            *(float2*)(C + (size_t)(row + 8) * DIM + col) = o1;
        }
    }
}

__global__ __launch_bounds__(256, 2)
void gemm_mma(const float* __restrict__ A, const float* __restrict__ W,
              const float* __restrict__ bias, float* __restrict__ C) {
    extern __shared__ char sm[];
    gemm_body(A, W, bias, C, sm);
}

__global__ __launch_bounds__(256, 2)
void gemm_mma_qkv(const float* __restrict__ A,
                  const float* __restrict__ W0, const float* __restrict__ b0,
                  float* __restrict__ C0,
                  const float* __restrict__ W1, const float* __restrict__ b1,
                  float* __restrict__ C1,
                  const float* __restrict__ W2, const float* __restrict__ b2,
                  float* __restrict__ C2) {
    extern __shared__ char sm[];
    const float* W = (blockIdx.z == 0) ? W0 : (blockIdx.z == 1) ? W1 : W2;
    const float* b = (blockIdx.z == 0) ? b0 : (blockIdx.z == 1) ? b1 : b2;
    float* C = (blockIdx.z == 0) ? C0 : (blockIdx.z == 1) ? C1 : C2;
    gemm_body(A, W, b, C, sm);
}

// ===========================================================================
// Attention: FA2-style mma.sync pure fp16, occ 2.
// S = Qh K_h^T;  O += Ph Vt_h.   fp32 accumulate everywhere (mma.f32).
// Block: one (b,h) x 128 queries, 8 warps, 16 query rows/warp.
// smem: Qh/Kh [128][144B rows], Vth [64][272B rows]  -> 54272 B/CTA.
// ===========================================================================
#define SQH 0
#define SKH 18432
#define SVH 36864
#define VTSTR 272
#define ATT_SMEM (SVH + 64 * VTSTR)   // 54272
#define QKSTR 144

__global__ __launch_bounds__(256, 2)
void attn_mma_kernel(const float* __restrict__ q, const float* __restrict__ k,
                     const float* __restrict__ v, float* __restrict__ ctx) {
    extern __shared__ char smc[];
    const int tid = threadIdx.x;
    const int wid = tid >> 5;
    const int lane = tid & 31;
    const int laneR = lane >> 2;
    const int laneC = lane & 3;
    const int b = blockIdx.x >> 4;
    const int h = blockIdx.x & 15;
    const int t0 = blockIdx.y * 128;
    const size_t base = (size_t)b * DIM + h * HD;
    const int mrow = wid * 16;

    // ---- load Q tile (128x64) -> fp16 ----
#pragma unroll
    for (int it = 0; it < 8; it++) {
        int task = tid + it * 256;
        int row = task >> 4;
        int c = (task & 15) << 2;
        float4 f = *(const float4*)(q + (size_t)(t0 + row) * ROWSTR + base + c);
        uint2 uh;
        uh.x = pack2(f.x, f.y);
        uh.y = pack2(f.z, f.w);
        *(uint2*)(smc + SQH + row * QKSTR + c * 2) = uh;
    }

    float oacc[8][4];
#pragma unroll
    for (int i = 0; i < 8; i++)
#pragma unroll
        for (int r = 0; r < 4; r++) oacc[i][r] = 0.f;
    float mr[2] = {-1e30f, -1e30f};
    float ls[2] = {0.f, 0.f};

    for (int kt = 0; kt < 8; kt++) {
        const int s0 = kt * 128;
        __syncthreads();

        // ---- K tile (128x64) -> fp16 ----
#pragma unroll
        for (int it = 0; it < 8; it++) {
            int task = tid + it * 256;
            int row = task >> 4;
            int c = (task & 15) << 2;
            float4 f = *(const float4*)(k + (size_t)(s0 + row) * ROWSTR + base + c);
            uint2 uh;
            uh.x = pack2(f.x, f.y);
            uh.y = pack2(f.z, f.w);
            *(uint2*)(smc + SKH + row * QKSTR + c * 2) = uh;
        }

        // ---- V tile transposed: Vt[d][s], s-pairs in u32 ----
#pragma unroll
        for (int it = 0; it < 4; it++) {
            int task = tid + it * 256;
            int sp = task >> 4;
            int d0 = (task & 15) << 2;
            const float* vp = v + (size_t)(s0 + 2 * sp) * ROWSTR + base + d0;
            float4 f0 = *(const float4*)vp;
            float4 f1 = *(const float4*)(vp + ROWSTR);
            float a0[4] = {f0.x, f0.y, f0.z, f0.w};
            float a1[4] = {f1.x, f1.y, f1.z, f1.w};
#pragma unroll
            for (int e = 0; e < 4; e++) {
                *(uint32_t*)(smc + SVH + (d0 + e) * VTSTR + sp * 4) =
                    pack2(a0[e], a1[e]);
            }
        }
        __syncthreads();

        // ---- S = Q K^T (16 rows x 128 keys), single pass ----
        float sacc[16][4];
#pragma unroll
        for (int nt = 0; nt < 16; nt++)
#pragma unroll
            for (int r = 0; r < 4; r++) sacc[nt][r] = 0.f;

#pragma unroll
        for (int ks = 0; ks < 4; ks++) {
            const uint32_t qb = (mrow + laneR) * QKSTR + ks * 32 + laneC * 4;
            uint32_t ah[4];
            ah[0] = *(const uint32_t*)(smc + SQH + qb);
            ah[1] = *(const uint32_t*)(smc + SQH + qb + 8 * QKSTR);
            ah[2] = *(const uint32_t*)(smc + SQH + qb + 16);
            ah[3] = *(const uint32_t*)(smc + SQH + qb + 8 * QKSTR + 16);
#pragma unroll
            for (int nt = 0; nt < 16; nt++) {
                const uint32_t kb =
                    (nt * 8 + laneR) * QKSTR + ks * 32 + laneC * 4;
                uint32_t bhf[2];
                bhf[0] = *(const uint32_t*)(smc + SKH + kb);
                bhf[1] = *(const uint32_t*)(smc + SKH + kb + 16);
                mma16816(sacc[nt], ah, bhf);
            }
        }

        // ---- online softmax ----
#pragma unroll
        for (int r = 0; r < 2; r++) {
            float mt = -1e30f;
#pragma unroll
            for (int nt = 0; nt < 16; nt++)
                mt = fmaxf(mt, fmaxf(sacc[nt][2 * r], sacc[nt][2 * r + 1]));
            mt = fmaxf(mt, __shfl_xor_sync(0xffffffffu, mt, 1));
            mt = fmaxf(mt, __shfl_xor_sync(0xffffffffu, mt, 2));
            float mnew = fmaxf(mr[r], mt);
            float corr = __expf((mr[r] - mnew) * 0.125f);
            mr[r] = mnew;
            const float mm = mnew * 0.125f;
            float rs = 0.f;
#pragma unroll
            for (int nt = 0; nt < 16; nt++) {
                float p0 = __expf(fmaf(sacc[nt][2 * r], 0.125f, -mm));
                float p1 = __expf(fmaf(sacc[nt][2 * r + 1], 0.125f, -mm));
                sacc[nt][2 * r] = p0;
                sacc[nt][2 * r + 1] = p1;
                rs += p0 + p1;
            }
            rs += __shfl_xor_sync(0xffffffffu, rs, 1);
            rs += __shfl_xor_sync(0xffffffffu, rs, 2);
            ls[r] = ls[r] * corr + rs;
#pragma unroll
            for (int nt2 = 0; nt2 < 8; nt2++) {
                oacc[nt2][2 * r] *= corr;
                oacc[nt2][2 * r + 1] *= corr;
            }
        }

        // ---- O += P @ V (single pass) ----
#pragma unroll
        for (int j = 0; j < 8; j++) {
            uint32_t ph[4];
            ph[0] = pack2(sacc[2 * j][0], sacc[2 * j][1]);
            ph[1] = pack2(sacc[2 * j][2], sacc[2 * j][3]);
            ph[2] = pack2(sacc[2 * j + 1][0], sacc[2 * j + 1][1]);
            ph[3] = pack2(sacc[2 * j + 1][2], sacc[2 * j + 1][3]);
#pragma unroll
            for (int nt2 = 0; nt2 < 8; nt2++) {
                const uint32_t vb =
                    (nt2 * 8 + laneR) * VTSTR + j * 32 + laneC * 4;
                uint32_t vhf[2];
                vhf[0] = *(const uint32_t*)(smc + SVH + vb);
                vhf[1] = *(const uint32_t*)(smc + SVH + vb + 16);
                mma16816(oacc[nt2], ph, vhf);
            }
        }
    }

    // ---- normalize and store ----
    const float inv0 = 1.f / ls[0];
    const float inv1 = 1.f / ls[1];
    const int r0 = t0 + mrow + laneR;
#pragma unroll
    for (int nt2 = 0; nt2 < 8; nt2++) {
        const size_t col = base + nt2 * 8 + laneC * 2;
        *(float2*)(ctx + (size_t)r0 * ROWSTR + col) =
            make_float2(oacc[nt2][0] * inv0, oacc[nt2][1] * inv0);
        *(float2*)(ctx + (size_t)(r0 + 8) * ROWSTR + col) =
            make_float2(oacc[nt2][2] * inv1, oacc[nt2][3] * inv1);
    }
}

// ===========================================================================
// Fused residual-add + LayerNorm over rows of 1024. One block per row.
// ===========================================================================
__global__ __launch_bounds__(256)
void add_ln_kernel(const float* __restrict__ a, const float* __restrict__ res,
                   const float* __restrict__ gma, const float* __restrict__ bta,
                   float* __restrict__ out) {
    __shared__ float red[16];
    const int row = blockIdx.x;
    const int tid = threadIdx.x;

    float4 va = *(const float4*)(a + (size_t)row * DIM + tid * 4);
    float4 vr = *(const float4*)(res + (size_t)row * DIM + tid * 4);
    float4 x;
    x.x = va.x + vr.x; x.y = va.y + vr.y; x.z = va.z + vr.z; x.w = va.w + vr.w;

    float sum = x.x + x.y + x.z + x.w;
    float sq = x.x * x.x + x.y * x.y + x.z * x.z + x.w * x.w;
#pragma unroll
    for (int d = 16; d; d >>= 1) {
        sum += __shfl_xor_sync(0xffffffffu, sum, d);
        sq += __shfl_xor_sync(0xffffffffu, sq, d);
    }
    const int warp = tid >> 5;
    if ((tid & 31) == 0) { red[warp] = sum; red[8 + warp] = sq; }
    __syncthreads();
    if (tid < 32) {
        float s = (tid < 8) ? red[tid] : 0.f;
        float q2 = (tid < 8) ? red[8 + tid] : 0.f;
#pragma unroll
        for (int d = 4; d; d >>= 1) {
            s += __shfl_xor_sync(0xffffffffu, s, d);
            q2 += __shfl_xor_sync(0xffffffffu, q2, d);
        }
        if (tid == 0) { red[0] = s; red[1] = q2; }
    }
    __syncthreads();
    const float mean = red[0] * (1.f / DIM);
    const float var = red[1] * (1.f / DIM) - mean * mean;
    const float rstd = rsqrtf(var + 1e-5f);

    float4 g4 = *(const float4*)(gma + tid * 4);
    float4 b4 = *(const float4*)(bta + tid * 4);
    float4 o;
    o.x = (x.x - mean) * rstd * g4.x + b4.x;
    o.y = (x.y - mean) * rstd * g4.y + b4.y;
    o.z = (x.z - mean) * rstd * g4.z + b4.z;
    o.w = (x.w - mean) * rstd * g4.w + b4.w;
    *(float4*)(out + (size_t)row * DIM + tid * 4) = o;
}

// ===========================================================================
// launch
// ===========================================================================
extern "C" void kernel_launch(void* const* d_in, const int* in_sizes, int n_in,
                              void* d_out, int out_size) {
    const float* x  = (const float*)d_in[0];
    const float* Wq = (const float*)d_in[1];
    const float* bq = (const float*)d_in[2];
    const float* Wk = (const float*)d_in[3];
    const float* bk = (const float*)d_in[4];
    const float* Wv = (const float*)d_in[5];
    const float* bv = (const float*)d_in[6];
    const float* Wo = (const float*)d_in[7];
    const float* bo = (const float*)d_in[8];
    const float* Wl = (const float*)d_in[9];
    const float* bl = (const float*)d_in[10];
    const float* g1 = (const float*)d_in[11];
    const float* b1 = (const float*)d_in[12];
    const float* g2 = (const float*)d_in[13];
    const float* b2 = (const float*)d_in[14];
    float* out = (float*)d_out;

    float *q, *k, *v, *ctx, *t1, *hh, *t2;
    cudaGetSymbolAddress((void**)&q, g_q);
    cudaGetSymbolAddress((void**)&k, g_k);
    cudaGetSymbolAddress((void**)&v, g_v);
    cudaGetSymbolAddress((void**)&ctx, g_ctx);
    cudaGetSymbolAddress((void**)&t1, g_t1);
    cudaGetSymbolAddress((void**)&hh, g_h);
    cudaGetSymbolAddress((void**)&t2, g_t2);

    cudaFuncSetAttribute(attn_mma_kernel,
                         cudaFuncAttributeMaxDynamicSharedMemorySize, ATT_SMEM);
    cudaFuncSetAttribute(gemm_mma,
                         cudaFuncAttributeMaxDynamicSharedMemorySize, GEMM_SMEM);
    cudaFuncSetAttribute(gemm_mma_qkv,
                         cudaFuncAttributeMaxDynamicSharedMemorySize, GEMM_SMEM);

    dim3 ggrid(DIM / 128, NTOK / 128);      // (8, 32)
    dim3 ggrid3(DIM / 128, NTOK / 128, 3);  // QKV batched
    dim3 gblk(256);

    gemm_mma_qkv<<<ggrid3, gblk, GEMM_SMEM>>>(x, Wq, bq, q, Wk, bk, k, Wv, bv, v);
    attn_mma_kernel<<<dim3(BB * NH, TT / 128), 256, ATT_SMEM>>>(q, k, v, ctx);
    gemm_mma<<<ggrid, gblk, GEMM_SMEM>>>(ctx, Wo, bo, t1);
    add_ln_kernel<<<NTOK, 256>>>(t1, x, g1, b1, hh);
    gemm_mma<<<ggrid, gblk, GEMM_SMEM>>>(hh, Wl, bl, t2);
    add_ln_kernel<<<NTOK, 256>>>(t2, hh, g2, b2, out);
}